// round 3
// baseline (speedup 1.0000x reference)
#include <cuda_runtime.h>
#include <cuda_bf16.h>
#include <stdint.h>

// ---------------------------------------------------------------------------
// Problem constants
// ---------------------------------------------------------------------------
#define BB     16384
#define DI     1024
#define DH     1024
#define KTOT   2048           // Di + Dh packed K
#define NROWS  4096           // 4*Dh gate rows (permuted)
#define TM     128
#define TN     128
#define KCH    32             // K elems per pipeline chunk
#define STAGES 4
#define THREADS 256
#define NKT    192            // 3 terms * (2048/32)
#define ROWB   80             // smem row stride bytes (32 bf16 = 64B + 16B pad)
#define STAGE_BYTES (256 * ROWB)          // 20480: A rows 0-127, B rows 128-255
#define SMEM_B_OFF  (128 * ROWB)          // 10240
#define SMEM_TOTAL  (STAGES * STAGE_BYTES)  // 81920

// ---------------------------------------------------------------------------
// Device scratch
// ---------------------------------------------------------------------------
__device__ __nv_bfloat16 g_Ah[(size_t)BB * KTOT];
__device__ __nv_bfloat16 g_Al[(size_t)BB * KTOT];
__device__ __nv_bfloat16 g_Bh[(size_t)NROWS * KTOT];
__device__ __nv_bfloat16 g_Bl[(size_t)NROWS * KTOT];

// ---------------------------------------------------------------------------
// PTX helpers (base-ISA only: no 'a'-suffix features)
// ---------------------------------------------------------------------------
__device__ __forceinline__ uint32_t smem_u32(const void* p) {
    uint32_t a;
    asm("{ .reg .u64 t; cvta.to.shared.u64 t, %1; cvt.u32.u64 %0, t; }"
        : "=r"(a) : "l"(p));
    return a;
}

__device__ __forceinline__ void cp_async16(uint32_t so, const void* gp) {
    asm volatile("cp.async.cg.shared.global [%0], [%1], 16;" :: "r"(so), "l"(gp));
}
#define CP_COMMIT() asm volatile("cp.async.commit_group;" ::: "memory")
#define CP_WAIT2()  asm volatile("cp.async.wait_group 2;" ::: "memory")

#define LDSM_X4(R, ADDR)                                                      \
    asm volatile("ldmatrix.sync.aligned.m8n8.x4.shared.b16 {%0,%1,%2,%3}, [%4];" \
                 : "=r"((R)[0]), "=r"((R)[1]), "=r"((R)[2]), "=r"((R)[3])     \
                 : "r"(ADDR))

#define MMA16816(C, A, B0, B1)                                                \
    asm volatile("mma.sync.aligned.m16n8k16.row.col.f32.bf16.bf16.f32 "       \
                 "{%0,%1,%2,%3},{%4,%5,%6,%7},{%8,%9},{%0,%1,%2,%3};"         \
                 : "+f"((C)[0]), "+f"((C)[1]), "+f"((C)[2]), "+f"((C)[3])     \
                 : "r"((A)[0]), "r"((A)[1]), "r"((A)[2]), "r"((A)[3]),        \
                   "r"(B0), "r"(B1))

__device__ __forceinline__ float sigf(float x)   { return 1.0f / (1.0f + __expf(-x)); }
__device__ __forceinline__ float tanh_f(float x) { return 1.0f - 2.0f / (__expf(2.0f * x) + 1.0f); }

// ---------------------------------------------------------------------------
// Prep kernels: pack fp32 inputs into bf16 hi/lo operands
// ---------------------------------------------------------------------------
__global__ void pack_A(const float* __restrict__ X, const float* __restrict__ h0) {
    size_t i = (size_t)blockIdx.x * blockDim.x + threadIdx.x;
    int k = (int)(i & (KTOT - 1));
    size_t b = i >> 11;
    float v = (k < DI) ? X[b * DI + k] : h0[b * DH + (k - DI)];
    __nv_bfloat16 hi = __float2bfloat16_rn(v);
    g_Ah[i] = hi;
    g_Al[i] = __float2bfloat16_rn(v - __bfloat162float(hi));
}

// Gate permutation matched to the mma.sync C-fragment layout:
// permuted row  np = 64*wb + 16*e + 8*s + 2*q + r
//   gate = 2*s + r   (0=i,1=f,2=g,3=o),  d = 16*wb + 4*e + q
//   source col n = gate*1024 + d;  B[np][k] = U[k][n] (k<1024) else W[n][k-1024]
__global__ void pack_B(const float* __restrict__ U, const float* __restrict__ W) {
    size_t i = (size_t)blockIdx.x * blockDim.x + threadIdx.x;
    int k  = (int)(i & (KTOT - 1));
    int np = (int)(i >> 11);
    int wb = np >> 6, e = (np >> 4) & 3, s = (np >> 3) & 1;
    int q = (np >> 1) & 3, r = np & 1;
    int gate = s * 2 + r;
    int d = wb * 16 + e * 4 + q;
    int n = gate * DH + d;
    float v = (k < DI) ? U[(size_t)k * NROWS + n] : W[(size_t)n * DH + (k - DI)];
    __nv_bfloat16 hi = __float2bfloat16_rn(v);
    g_Bh[i] = hi;
    g_Bl[i] = __float2bfloat16_rn(v - __bfloat162float(hi));
}

// ---------------------------------------------------------------------------
// Main GEMM + fused LSTM epilogue (mma.sync bf16, 3-term hi/lo accumulation)
// ---------------------------------------------------------------------------
__device__ __forceinline__ void load_stage(uint32_t sstage, int kt, int mbase,
                                           int nbase, int tid) {
    int term = kt >> 6;                    // 0: Ah*Bh, 1: Ah*Bl, 2: Al*Bh
    int kk   = (kt & 63) * KCH;
    const __nv_bfloat16* Asrc = (term < 2) ? g_Ah : g_Al;
    const __nv_bfloat16* Bsrc = (term == 1) ? g_Bl : g_Bh;
    int r = tid >> 2;                      // 0..63
    int c = tid & 3;                       // 16B chunk within 64B row
#pragma unroll
    for (int h = 0; h < 2; h++) {
        int row = r + h * 64;
        cp_async16(sstage + row * ROWB + c * 16,
                   Asrc + (size_t)(mbase + row) * KTOT + kk + c * 8);
    }
#pragma unroll
    for (int h = 0; h < 2; h++) {
        int row = r + h * 64;
        cp_async16(sstage + SMEM_B_OFF + row * ROWB + c * 16,
                   Bsrc + (size_t)(nbase + row) * KTOT + kk + c * 8);
    }
    CP_COMMIT();
}

__global__ void __launch_bounds__(THREADS)
lstm_gemm(const float* __restrict__ c0, float* __restrict__ outh,
          float* __restrict__ outc) {
    extern __shared__ char smem[];
    uint32_t sbase = smem_u32(smem);
    int tid  = threadIdx.x;
    int lane = tid & 31, wid = tid >> 5;
    int wm = wid & 3, wn = wid >> 2;        // warp grid 4 (m) x 2 (n)
    int mbase = blockIdx.y * TM;
    int nbase = blockIdx.x * TN;

    // Per-lane ldmatrix base offsets (bytes, within a stage)
    // A x4: matrices (m0,k0),(m8,k0),(m0,k8),(m8,k8); lane j=lane>>3 selects matrix
    uint32_t aoff = (uint32_t)(wm * 32 + (lane & 7) + ((lane >> 3) & 1) * 8) * ROWB
                    + ((lane >> 4) & 1) * 16;
    // B x4: matrices (g0,k0),(g0,k8),(g1,k0),(g1,k8)
    uint32_t boff = SMEM_B_OFF
                    + (uint32_t)(wn * 64 + (lane & 7) + ((lane >> 4) & 1) * 8) * ROWB
                    + ((lane >> 3) & 1) * 16;

    float acc[2][8][4];
#pragma unroll
    for (int mt = 0; mt < 2; mt++)
#pragma unroll
        for (int ng = 0; ng < 8; ng++)
#pragma unroll
            for (int j = 0; j < 4; j++) acc[mt][ng][j] = 0.0f;

    // Prologue: stages 0..2
    for (int kt = 0; kt < STAGES - 1; kt++)
        load_stage(sbase + (kt & 3) * STAGE_BYTES, kt, mbase, nbase, tid);

#pragma unroll 1
    for (int kt = 0; kt < NKT; kt++) {
        CP_WAIT2();
        __syncthreads();

        int ktl = kt + STAGES - 1;
        if (ktl < NKT)
            load_stage(sbase + (ktl & 3) * STAGE_BYTES, ktl, mbase, nbase, tid);
        else
            CP_COMMIT();   // keep group count uniform for CP_WAIT2

        uint32_t sa = sbase + (kt & 3) * STAGE_BYTES;
#pragma unroll
        for (int ks = 0; ks < 2; ks++) {
            uint32_t a0[4], a1[4], b[8][2];
            LDSM_X4(a0, sa + aoff + ks * 32);
            LDSM_X4(a1, sa + aoff + 16 * ROWB + ks * 32);
#pragma unroll
            for (int gp = 0; gp < 4; gp++) {
                uint32_t t[4];
                LDSM_X4(t, sa + boff + gp * 16 * ROWB + ks * 32);
                b[2 * gp][0] = t[0]; b[2 * gp][1] = t[1];
                b[2 * gp + 1][0] = t[2]; b[2 * gp + 1][1] = t[3];
            }
#pragma unroll
            for (int ng = 0; ng < 8; ng++) {
                MMA16816(acc[0][ng], a0, b[ng][0], b[ng][1]);
                MMA16816(acc[1][ng], a1, b[ng][0], b[ng][1]);
            }
        }
    }

    // ---- Fused LSTM epilogue (pure register math; gates land per-thread) ----
    int q = lane & 3;
    int wbg = blockIdx.x * 2 + wn;
#pragma unroll
    for (int mt = 0; mt < 2; mt++) {
#pragma unroll
        for (int e = 0; e < 4; e++) {
#pragma unroll
            for (int rs = 0; rs < 2; rs++) {
                float gi = sigf(acc[mt][2 * e][rs * 2 + 0]);
                float gf = sigf(acc[mt][2 * e][rs * 2 + 1]);
                float gg = tanh_f(acc[mt][2 * e + 1][rs * 2 + 0]);
                float go = sigf(acc[mt][2 * e + 1][rs * 2 + 1]);
                int m = mbase + wm * 32 + mt * 16 + (lane >> 2) + rs * 8;
                int d = wbg * 16 + e * 4 + q;
                size_t idx = (size_t)m * DH + d;
                float c0v = __ldg(&c0[idx]);
                float cn = gf * c0v + gi * gg;
                float hn = go * tanh_f(cn);
                outh[idx] = hn;
                outc[idx] = cn;
            }
        }
    }
}

// ---------------------------------------------------------------------------
// Launch
// ---------------------------------------------------------------------------
extern "C" void kernel_launch(void* const* d_in, const int* in_sizes, int n_in,
                              void* d_out, int out_size) {
    const float* X  = (const float*)d_in[0];
    const float* h0 = (const float*)d_in[1];
    const float* c0 = (const float*)d_in[2];
    const float* U  = (const float*)d_in[3];
    const float* W  = (const float*)d_in[4];
    float* outh = (float*)d_out;
    float* outc = outh + (size_t)BB * DH;

    pack_A<<<(BB * KTOT) / 256, 256>>>(X, h0);
    pack_B<<<(NROWS * KTOT) / 256, 256>>>(U, W);

    cudaFuncSetAttribute(lstm_gemm, cudaFuncAttributeMaxDynamicSharedMemorySize,
                         SMEM_TOTAL);
    dim3 grid(NROWS / TN, BB / TM);
    lstm_gemm<<<grid, THREADS, SMEM_TOTAL>>>(c0, outh, outc);
}